// round 1
// baseline (speedup 1.0000x reference)
#include <cuda_runtime.h>
#include <cuda_bf16.h>
#include <math.h>

#define D_FIX 256
#define C_MAX 50176
#define B_MAX 512

// ---- device scratch (allocation-free: __device__ globals) ----
__device__ __nv_bfloat16 g_tn[(size_t)C_MAX * D_FIX];   // normalized text feats, bf16
__device__ __nv_bfloat16 g_vn[(size_t)B_MAX * D_FIX];   // normalized visual feats, bf16
__device__ float g_denom[B_MAX];
__device__ float g_pos[B_MAX];
__device__ int   g_npos[B_MAX];
__device__ unsigned char g_loaded[C_MAX];

// ---------------------------------------------------------------------------
__global__ void zero_kernel(int B, int C) {
    int i = blockIdx.x * blockDim.x + threadIdx.x;
    if (i < C) g_loaded[i] = 0;
    if (i < B) { g_denom[i] = 0.f; g_pos[i] = 0.f; g_npos[i] = 0; }
}

__global__ void mask_kernel(const int* __restrict__ ids, int n, int C) {
    int i = blockIdx.x * blockDim.x + threadIdx.x;
    if (i < n) {
        int c = ids[i];
        if (c >= 0 && c < C) g_loaded[c] = 1;
    }
}

// normalize rows of x [rows, D]; write bf16 into g_vn (which=0) or g_tn (which=1)
__global__ void norm_rows_kernel(const float* __restrict__ x, int rows, int D,
                                 float eps, int which) {
    int row = blockIdx.x;
    if (row >= rows) return;
    const float* xr = x + (size_t)row * D;
    float ss = 0.f;
    for (int d = threadIdx.x; d < D; d += blockDim.x) { float v = xr[d]; ss += v * v; }
#pragma unroll
    for (int o = 16; o > 0; o >>= 1) ss += __shfl_xor_sync(0xffffffffu, ss, o);
    __shared__ float wsum[8];
    int lane = threadIdx.x & 31, w = threadIdx.x >> 5;
    if (lane == 0) wsum[w] = ss;
    __syncthreads();
    float tot = 0.f;
    int nw = blockDim.x >> 5;
    for (int i = 0; i < nw; ++i) tot += wsum[i];
    float inv = 1.0f / (eps + sqrtf(tot));
    __nv_bfloat16* dst = which ? g_tn : g_vn;
    for (int d = threadIdx.x; d < D; d += blockDim.x)
        dst[(size_t)row * D + d] = __float2bfloat16(xr[d] * inv);
}

// ---------------------------------------------------------------------------
__device__ __forceinline__ void mma_bf16(float c[4], const unsigned a[4],
                                         unsigned b0, unsigned b1) {
    asm volatile(
        "mma.sync.aligned.m16n8k16.row.col.f32.bf16.bf16.f32 "
        "{%0,%1,%2,%3}, {%4,%5,%6,%7}, {%8,%9}, {%0,%1,%2,%3};\n"
        : "+f"(c[0]), "+f"(c[1]), "+f"(c[2]), "+f"(c[3])
        : "r"(a[0]), "r"(a[1]), "r"(a[2]), "r"(a[3]), "r"(b0), "r"(b1));
}

// BM=128 x BN=128 tile, K looped in BK=64 chunks, 8 warps (4 m-slices x 2 n-slices),
// warp tile 32x64 via m16n8k16. Fused masked-softmax statistics epilogue.
__global__ __launch_bounds__(256, 2)
void gemm_loss_kernel(const int* __restrict__ label, int B, int C, int D) {
    __shared__ __align__(16) __nv_bfloat16 As[128][72];
    __shared__ __align__(16) __nv_bfloat16 Bs[128][72];
    __shared__ float sdn[128], sps[128];
    __shared__ int sns[128];
    __shared__ unsigned char loaded_s[128];

    const int tid = threadIdx.x;
    const int cbase = blockIdx.x * 128;
    const int rbase = blockIdx.y * 128;

    if (tid < 128) {
        int c = cbase + tid;
        loaded_s[tid] = (c < C) ? g_loaded[c] : (unsigned char)0;
        sdn[tid] = 0.f; sps[tid] = 0.f; sns[tid] = 0;
    }

    float acc[2][8][4];
#pragma unroll
    for (int i = 0; i < 2; i++)
#pragma unroll
        for (int j = 0; j < 8; j++)
#pragma unroll
            for (int k = 0; k < 4; k++) acc[i][j][k] = 0.f;

    const int lane = tid & 31, wid = tid >> 5;
    const int g = lane >> 2, tig = lane & 3;
    const int warp_m = wid & 3, warp_n = wid >> 2;

    const int nbk = D >> 6;          // BK = 64
    for (int bk = 0; bk < nbk; ++bk) {
        __syncthreads();
#pragma unroll
        for (int p = 0; p < 4; ++p) {
            int idx = p * 256 + tid;     // 1024 uint4 slots per operand
            int r = idx >> 3, s = idx & 7;
            uint4 va = make_uint4(0, 0, 0, 0);
            int grow = rbase + r;
            if (grow < B)
                va = *(const uint4*)&g_vn[(size_t)grow * D + bk * 64 + s * 8];
            *(uint4*)&As[r][s * 8] = va;
            uint4 vb = make_uint4(0, 0, 0, 0);
            int gc = cbase + r;
            if (gc < C)
                vb = *(const uint4*)&g_tn[(size_t)gc * D + bk * 64 + s * 8];
            *(uint4*)&Bs[r][s * 8] = vb;
        }
        __syncthreads();

#pragma unroll
        for (int ks = 0; ks < 4; ++ks) {
            const int k0 = ks * 16;
            unsigned a[2][4];
#pragma unroll
            for (int mt = 0; mt < 2; ++mt) {
                int ar = warp_m * 32 + mt * 16;
                a[mt][0] = *(const unsigned*)&As[ar + g    ][k0 + 2 * tig];
                a[mt][1] = *(const unsigned*)&As[ar + g + 8][k0 + 2 * tig];
                a[mt][2] = *(const unsigned*)&As[ar + g    ][k0 + 2 * tig + 8];
                a[mt][3] = *(const unsigned*)&As[ar + g + 8][k0 + 2 * tig + 8];
            }
#pragma unroll
            for (int nt = 0; nt < 8; ++nt) {
                int bc = warp_n * 64 + nt * 8 + g;
                unsigned b0 = *(const unsigned*)&Bs[bc][k0 + 2 * tig];
                unsigned b1 = *(const unsigned*)&Bs[bc][k0 + 2 * tig + 8];
                mma_bf16(acc[0][nt], a[0], b0, b1);
                mma_bf16(acc[1][nt], a[1], b0, b1);
            }
        }
    }
    __syncthreads();

    // ---- epilogue: masked exp-sum / pos-sum / pos-count per row ----
#pragma unroll
    for (int mt = 0; mt < 2; ++mt) {
#pragma unroll
        for (int h = 0; h < 2; ++h) {
            int rl = warp_m * 32 + mt * 16 + h * 8 + g;
            int grow = rbase + rl;
            float dsum = 0.f, psum = 0.f; int np = 0;
            if (grow < B) {
                const int* lrow = label + (size_t)grow * C;
#pragma unroll
                for (int nt = 0; nt < 8; ++nt) {
                    int cl = warp_n * 64 + nt * 8 + 2 * tig;
#pragma unroll
                    for (int q = 0; q < 2; ++q) {
                        int c = cbase + cl + q;
                        if (c < C && loaded_s[cl + q]) {
                            float s = acc[mt][nt][h * 2 + q];
                            int lab = lrow[c];
                            if (lab != 0) { psum += s; np += 1; }
                            else          dsum += __expf(s);
                        }
                    }
                }
            }
#pragma unroll
            for (int o = 1; o <= 2; o <<= 1) {
                dsum += __shfl_xor_sync(0xffffffffu, dsum, o);
                psum += __shfl_xor_sync(0xffffffffu, psum, o);
                np   += __shfl_xor_sync(0xffffffffu, np, o);
            }
            if (tig == 0) {
                atomicAdd(&sdn[rl], dsum);
                atomicAdd(&sps[rl], psum);
                atomicAdd(&sns[rl], np);
            }
        }
    }
    __syncthreads();
    if (tid < 128) {
        int grow = rbase + tid;
        if (grow < B) {
            atomicAdd(&g_denom[grow], sdn[tid]);
            atomicAdd(&g_pos[grow], sps[tid]);
            atomicAdd(&g_npos[grow], sns[tid]);
        }
    }
}

// ---------------------------------------------------------------------------
__global__ void finalize_kernel(float* __restrict__ out, int B) {
    __shared__ float red[256];
    int t = threadIdx.x;
    float v = 0.f;
    for (int r = t; r < B; r += 256)
        v += logf(g_denom[r]) - g_pos[r] / (float)g_npos[r];
    red[t] = v;
    __syncthreads();
    for (int s = 128; s > 0; s >>= 1) {
        if (t < s) red[t] += red[t + s];
        __syncthreads();
    }
    if (t == 0) out[0] = red[0] / (float)B;
}

// ---------------------------------------------------------------------------
extern "C" void kernel_launch(void* const* d_in, const int* in_sizes, int n_in,
                              void* d_out, int out_size) {
    const float* vfeat = (const float*)d_in[0];
    const float* tfeat = (const float*)d_in[1];
    const int*   label = (const int*)d_in[2];
    const int*   ids   = (const int*)d_in[3];
    (void)n_in; (void)out_size;

    // derive shapes: s0=B*D, s1=C*D, s2=B*C  ->  D = sqrt(s0*s1/s2)
    double s0 = (double)in_sizes[0], s1 = (double)in_sizes[1], s2 = (double)in_sizes[2];
    int D = (int)(sqrt(s0 * s1 / s2) + 0.5);
    if (D <= 0) D = D_FIX;
    int B  = in_sizes[0] / D;
    int C  = in_sizes[1] / D;
    int NL = in_sizes[3];
    float* out = (float*)d_out;

    int mx = (C > B) ? C : B;
    zero_kernel<<<(mx + 255) / 256, 256>>>(B, C);
    mask_kernel<<<(NL + 255) / 256, 256>>>(ids, NL, C);
    norm_rows_kernel<<<B, 256>>>(vfeat, B, D, 0.0f, 0);
    norm_rows_kernel<<<C, 256>>>(tfeat, C, D, 1e-6f, 1);

    dim3 grid((C + 127) / 128, (B + 127) / 128);
    gemm_loss_kernel<<<grid, 256>>>(label, B, C, D);

    finalize_kernel<<<1, 256>>>(out, B);
}

// round 2
// speedup vs baseline: 1.4181x; 1.4181x over previous
#include <cuda_runtime.h>
#include <cuda_bf16.h>
#include <math.h>

#define D_FIX 256
#define C_MAX 50176
#define B_MAX 512
#define W_MAX ((C_MAX / 128) * 4)   // mask words per row (1568)

// ---- device scratch (allocation-free: __device__ globals) ----
__device__ __nv_bfloat16 g_tn[(size_t)C_MAX * D_FIX];   // normalized text feats, bf16
__device__ __nv_bfloat16 g_vn[(size_t)B_MAX * D_FIX];   // normalized visual feats, bf16
__device__ float g_denom[B_MAX];
__device__ float g_pos[B_MAX];
__device__ int   g_npos[B_MAX];
__device__ unsigned char g_loaded[C_MAX];
__device__ unsigned g_posw[(size_t)B_MAX * W_MAX];      // pos bitmask
__device__ unsigned g_negw[(size_t)B_MAX * W_MAX];      // neg bitmask

// ---------------------------------------------------------------------------
__global__ void zero_kernel(int B, int C, int padElems) {
    int i = blockIdx.x * blockDim.x + threadIdx.x;
    if (i < C) g_loaded[i] = 0;
    if (i < B) { g_denom[i] = 0.f; g_pos[i] = 0.f; g_npos[i] = 0; }
    if (i < padElems) g_tn[(size_t)C * D_FIX + i] = __float2bfloat16(0.f);
}

__global__ void mask_kernel(const int* __restrict__ ids, int n, int C) {
    int i = blockIdx.x * blockDim.x + threadIdx.x;
    if (i < n) {
        int c = ids[i];
        if (c >= 0 && c < C) g_loaded[c] = 1;
    }
}

// pack labels+loaded into pos/neg bitmasks: one bit per (row, class)
#define WPW 8   // words per warp
__global__ void pack_kernel(const int* __restrict__ label, int B, int C, int W) {
    int row  = blockIdx.y;
    int warp = threadIdx.x >> 5, lane = threadIdx.x & 31;
    int word0 = (blockIdx.x * 8 + warp) * WPW;
    const int* lrow = label + (size_t)row * C;
    unsigned* prow = g_posw + (size_t)row * W;
    unsigned* nrow = g_negw + (size_t)row * W;
#pragma unroll
    for (int k = 0; k < WPW; ++k) {
        int w = word0 + k;
        if (w >= W) break;
        int c = w * 32 + lane;
        bool inC = (c < C);
        bool ld  = inC && (g_loaded[c] != 0);
        int lab  = inC ? lrow[c] : 0;
        unsigned pos = __ballot_sync(0xffffffffu, ld && lab != 0);
        unsigned neg = __ballot_sync(0xffffffffu, ld && lab == 0);
        if (lane == 0) { prow[w] = pos; nrow[w] = neg; }
    }
}

// warp-per-row normalize: x [rows, D] f32 -> bf16 into g_vn (which=0) / g_tn (1)
__global__ void norm_rows_kernel(const float* __restrict__ x, int rows, int D,
                                 float eps, int which) {
    int row = blockIdx.x * 8 + (threadIdx.x >> 5);
    if (row >= rows) return;
    int lane = threadIdx.x & 31;
    const float4* xr = (const float4*)(x + (size_t)row * D);
    int n4 = D >> 2;
    float ss = 0.f;
    for (int i = lane; i < n4; i += 32) {
        float4 t = xr[i];
        ss += t.x * t.x + t.y * t.y + t.z * t.z + t.w * t.w;
    }
#pragma unroll
    for (int o = 16; o > 0; o >>= 1) ss += __shfl_xor_sync(0xffffffffu, ss, o);
    float inv = 1.0f / (eps + sqrtf(ss));
    __nv_bfloat162* drow =
        (which ? (__nv_bfloat162*)g_tn : (__nv_bfloat162*)g_vn) + (size_t)row * (D >> 1);
    for (int i = lane; i < n4; i += 32) {
        float4 t = xr[i];
        drow[2 * i]     = __float22bfloat162_rn(make_float2(t.x * inv, t.y * inv));
        drow[2 * i + 1] = __float22bfloat162_rn(make_float2(t.z * inv, t.w * inv));
    }
}

// ---------------------------------------------------------------------------
__device__ __forceinline__ void mma_bf16(float c[4], const unsigned a[4],
                                         unsigned b0, unsigned b1) {
    asm volatile(
        "mma.sync.aligned.m16n8k16.row.col.f32.bf16.bf16.f32 "
        "{%0,%1,%2,%3}, {%4,%5,%6,%7}, {%8,%9}, {%0,%1,%2,%3};\n"
        : "+f"(c[0]), "+f"(c[1]), "+f"(c[2]), "+f"(c[3])
        : "r"(a[0]), "r"(a[1]), "r"(a[2]), "r"(a[3]), "r"(b0), "r"(b1));
}

__device__ __forceinline__ unsigned smemu32(const void* p) {
    return (unsigned)__cvta_generic_to_shared(p);
}

#define CP_ASYNC16(dst, src) \
    asm volatile("cp.async.cg.shared.global [%0], [%1], 16;\n" :: "r"(dst), "l"(src))
#define CP_COMMIT()  asm volatile("cp.async.commit_group;\n")

// BM=128 x BN=128, BK=64, 2-stage cp.async pipeline, ldmatrix fragments,
// 8 warps (4 m x 2 n), warp tile 32x64 via m16n8k16, bitmask epilogue.
#define A_ELE (128 * 72)                 // elements per operand per stage
__global__ __launch_bounds__(256, 2)
void gemm_loss_kernel(int B, int C, int D, int W) {
    extern __shared__ __nv_bfloat16 dyns[];
    __shared__ float sdn[128], sps[128];
    __shared__ int sns[128];
    __shared__ unsigned s_pos[128][4], s_neg[128][4];

    const int tid = threadIdx.x;
    const int cbase = blockIdx.x * 128;
    const int rbase = blockIdx.y * 128;

    if (tid < 128) { sdn[tid] = 0.f; sps[tid] = 0.f; sns[tid] = 0; }

    float acc[2][8][4];
#pragma unroll
    for (int i = 0; i < 2; i++)
#pragma unroll
        for (int j = 0; j < 8; j++)
#pragma unroll
            for (int k = 0; k < 4; k++) acc[i][j][k] = 0.f;

    const int lane = tid & 31, wid = tid >> 5;
    const int g = lane >> 2, tig = lane & 3;
    const int warp_m = wid & 3, warp_n = wid >> 2;
    const int grp = lane >> 3, rin = lane & 7;

    // loader (each thread copies 4x16B per operand per stage)
    const int lr = tid >> 3, ls = tid & 7;       // row/col-chunk pattern base
    auto load_stage = [&](int stage, int bk) {
        unsigned baseA = smemu32(dyns) + stage * (2 * A_ELE * 2);
        unsigned baseB = baseA + A_ELE * 2;
#pragma unroll
        for (int p = 0; p < 4; ++p) {
            int r = lr + p * 32, s = ls;
            unsigned off = (unsigned)(r * 72 + s * 8) * 2;
            CP_ASYNC16(baseA + off, &g_vn[(size_t)(rbase + r) * D + bk * 64 + s * 8]);
            CP_ASYNC16(baseB + off, &g_tn[(size_t)(cbase + r) * D + bk * 64 + s * 8]);
        }
    };

    const int nbk = D >> 6;
    load_stage(0, 0);
    CP_COMMIT();

    for (int bk = 0; bk < nbk; ++bk) {
        if (bk + 1 < nbk) { load_stage((bk + 1) & 1, bk + 1); CP_COMMIT(); }
        if (bk + 1 < nbk) { asm volatile("cp.async.wait_group 1;\n"); }
        else              { asm volatile("cp.async.wait_group 0;\n"); }
        __syncthreads();

        const __nv_bfloat16* As_s = dyns + (bk & 1) * 2 * A_ELE;
        const __nv_bfloat16* Bs_s = As_s + A_ELE;

        // per-thread ldmatrix base addresses for this stage
        // A: groups (rows 0-7,k0)(rows 8-15,k0)(rows 0-7,k0+8)(rows 8-15,k0+8)
        unsigned aBase[2], bBase[4];
#pragma unroll
        for (int mt = 0; mt < 2; ++mt) {
            int rowA = warp_m * 32 + mt * 16 + (grp & 1) * 8 + rin;
            int colA = (grp >> 1) * 8;
            aBase[mt] = smemu32(&As_s[rowA * 72 + colA]);
        }
#pragma unroll
        for (int p = 0; p < 4; ++p) {
            int rowB = warp_n * 64 + p * 16 + ((grp & 2) ? 8 : 0) + rin;
            int colB = (grp & 1) * 8;
            bBase[p] = smemu32(&Bs_s[rowB * 72 + colB]);
        }

#pragma unroll
        for (int ks = 0; ks < 4; ++ks) {
            const unsigned kof = ks * 16 * 2;   // bytes
            unsigned a[2][4];
#pragma unroll
            for (int mt = 0; mt < 2; ++mt)
                asm volatile(
                    "ldmatrix.sync.aligned.m8n8.x4.shared.b16 {%0,%1,%2,%3}, [%4];\n"
                    : "=r"(a[mt][0]), "=r"(a[mt][1]), "=r"(a[mt][2]), "=r"(a[mt][3])
                    : "r"(aBase[mt] + kof));
#pragma unroll
            for (int p = 0; p < 4; ++p) {
                unsigned b0, b1, b2, b3;
                asm volatile(
                    "ldmatrix.sync.aligned.m8n8.x4.shared.b16 {%0,%1,%2,%3}, [%4];\n"
                    : "=r"(b0), "=r"(b1), "=r"(b2), "=r"(b3)
                    : "r"(bBase[p] + kof));
                mma_bf16(acc[0][2 * p],     a[0], b0, b1);
                mma_bf16(acc[1][2 * p],     a[1], b0, b1);
                mma_bf16(acc[0][2 * p + 1], a[0], b2, b3);
                mma_bf16(acc[1][2 * p + 1], a[1], b2, b3);
            }
        }
        __syncthreads();
    }

    // ---- load this tile's pos/neg mask words into shared ----
    for (int i = tid; i < 512; i += 256) {
        int r = i >> 2, w = i & 3;
        size_t gi = (size_t)(rbase + r) * W + blockIdx.x * 4 + w;
        s_pos[r][w] = g_posw[gi];
        s_neg[r][w] = g_negw[gi];
    }
    __syncthreads();

    // ---- epilogue: masked exp-sum / pos-sum / pos-count per row ----
#pragma unroll
    for (int mt = 0; mt < 2; ++mt) {
#pragma unroll
        for (int h = 0; h < 2; ++h) {
            int rl = warp_m * 32 + mt * 16 + h * 8 + g;
            unsigned pw[4], nw[4];
#pragma unroll
            for (int w = 0; w < 4; ++w) { pw[w] = s_pos[rl][w]; nw[w] = s_neg[rl][w]; }
            float dsum = 0.f, psum = 0.f; int np = 0;
#pragma unroll
            for (int nt = 0; nt < 8; ++nt) {
#pragma unroll
                for (int q = 0; q < 2; ++q) {
                    int cl = warp_n * 64 + nt * 8 + 2 * tig + q;
                    int wi = cl >> 5;
                    unsigned m = 1u << (cl & 31);
                    float s = acc[mt][nt][h * 2 + q];
                    if (pw[wi] & m) { psum += s; np += 1; }
                    else if (nw[wi] & m) dsum += __expf(s);
                }
            }
#pragma unroll
            for (int o = 1; o <= 2; o <<= 1) {
                dsum += __shfl_xor_sync(0xffffffffu, dsum, o);
                psum += __shfl_xor_sync(0xffffffffu, psum, o);
                np   += __shfl_xor_sync(0xffffffffu, np, o);
            }
            if (tig == 0) {
                atomicAdd(&sdn[rl], dsum);
                atomicAdd(&sps[rl], psum);
                atomicAdd(&sns[rl], np);
            }
        }
    }
    __syncthreads();
    if (tid < 128) {
        int grow = rbase + tid;
        if (grow < B) {
            atomicAdd(&g_denom[grow], sdn[tid]);
            atomicAdd(&g_pos[grow], sps[tid]);
            atomicAdd(&g_npos[grow], sns[tid]);
        }
    }
}

// ---------------------------------------------------------------------------
__global__ void finalize_kernel(float* __restrict__ out, int B) {
    __shared__ float red[256];
    int t = threadIdx.x;
    float v = 0.f;
    for (int r = t; r < B; r += 256)
        v += logf(g_denom[r]) - g_pos[r] / (float)g_npos[r];
    red[t] = v;
    __syncthreads();
    for (int s = 128; s > 0; s >>= 1) {
        if (t < s) red[t] += red[t + s];
        __syncthreads();
    }
    if (t == 0) out[0] = red[0] / (float)B;
}

// ---------------------------------------------------------------------------
extern "C" void kernel_launch(void* const* d_in, const int* in_sizes, int n_in,
                              void* d_out, int out_size) {
    const float* vfeat = (const float*)d_in[0];
    const float* tfeat = (const float*)d_in[1];
    const int*   label = (const int*)d_in[2];
    const int*   ids   = (const int*)d_in[3];
    (void)n_in; (void)out_size;

    double s0 = (double)in_sizes[0], s1 = (double)in_sizes[1], s2 = (double)in_sizes[2];
    int D = (int)(sqrt(s0 * s1 / s2) + 0.5);
    if (D <= 0) D = D_FIX;
    int B  = in_sizes[0] / D;
    int C  = in_sizes[1] / D;
    int NL = in_sizes[3];
    float* out = (float*)d_out;

    int ctiles = (C + 127) / 128;
    int W = ctiles * 4;
    int padElems = (ctiles * 128 - C) * D;

    int mx = (C > B) ? C : B;
    if (padElems > mx) mx = padElems;
    zero_kernel<<<(mx + 255) / 256, 256>>>(B, C, padElems);
    mask_kernel<<<(NL + 255) / 256, 256>>>(ids, NL, C);

    norm_rows_kernel<<<(B + 7) / 8, 256>>>(vfeat, B, D, 0.0f, 0);
    norm_rows_kernel<<<(C + 7) / 8, 256>>>(tfeat, C, D, 1e-6f, 1);

    dim3 pgrid((W + 8 * WPW - 1) / (8 * WPW), B);
    pack_kernel<<<pgrid, 256>>>(label, B, C, W);

    static int smem_set = 0;
    size_t smem_bytes = 2 * 2 * (size_t)A_ELE * sizeof(__nv_bfloat16); // 73728
    cudaFuncSetAttribute(gemm_loss_kernel,
                         cudaFuncAttributeMaxDynamicSharedMemorySize,
                         (int)smem_bytes);
    (void)smem_set;

    dim3 grid(ctiles, (B + 127) / 128);
    gemm_loss_kernel<<<grid, 256, smem_bytes>>>(B, C, D, W);

    finalize_kernel<<<1, 256>>>(out, B);
}

// round 5
// speedup vs baseline: 1.6749x; 1.1811x over previous
#include <cuda_runtime.h>
#include <cuda_bf16.h>
#include <math.h>
#include <cstdint>

#define D_FIX 256
#define C_MAX 50176
#define B_MAX 512
#define W_MAX ((C_MAX / 128) * 4)
#define TS 272          // smem tile row stride in bytes (256 data + 16 pad)

// ---- device scratch (allocation-free: __device__ globals) ----
__device__ unsigned char g_tn8[(size_t)C_MAX * D_FIX];   // fp8 text (compact, x16)
__device__ unsigned char g_vn8[(size_t)B_MAX * D_FIX];   // fp8 visual (x16)
__device__ float g_denom[B_MAX];
__device__ float g_pos[B_MAX];
__device__ int   g_npos[B_MAX];
__device__ unsigned g_posw[(size_t)B_MAX * W_MAX];       // pos bits, compact space
__device__ unsigned g_negw[(size_t)B_MAX * W_MAX];       // neg bits, compact space

// ---------------------------------------------------------------------------
__device__ __forceinline__ unsigned smemu32(const void* p) {
    return (unsigned)__cvta_generic_to_shared(p);
}
#define CP_ASYNC16(dst, src) \
    asm volatile("cp.async.cg.shared.global [%0], [%1], 16;\n" :: "r"(dst), "l"(src))
#define CP_COMMIT()  asm volatile("cp.async.commit_group;\n")
#define CP_WAIT0()   asm volatile("cp.async.wait_group 0;\n" ::: "memory")

// pack 4 floats -> 4 e4m3 bytes (byte0 = a); cvt.e4m3x2 writes a b16 dest
__device__ __forceinline__ unsigned pack_e4m3x4(float a, float b, float c, float d) {
    unsigned short lo, hi;
    asm("cvt.rn.satfinite.e4m3x2.f32 %0, %1, %2;" : "=h"(lo) : "f"(b), "f"(a));
    asm("cvt.rn.satfinite.e4m3x2.f32 %0, %1, %2;" : "=h"(hi) : "f"(d), "f"(c));
    return ((unsigned)hi << 16) | (unsigned)lo;
}

__device__ __forceinline__ void mma_e4m3(float c[4], const unsigned a[4],
                                         unsigned b0, unsigned b1) {
    asm volatile(
        "mma.sync.aligned.m16n8k32.row.col.f32.e4m3.e4m3.f32 "
        "{%0,%1,%2,%3}, {%4,%5,%6,%7}, {%8,%9}, {%0,%1,%2,%3};\n"
        : "+f"(c[0]), "+f"(c[1]), "+f"(c[2]), "+f"(c[3])
        : "r"(a[0]), "r"(a[1]), "r"(a[2]), "r"(a[3]), "r"(b0), "r"(b1));
}

// ---------------------------------------------------------------------------
__global__ void zero_kernel(int B, int padBytes, size_t padOff) {
    int i = blockIdx.x * blockDim.x + threadIdx.x;
    if (i < B) { g_denom[i] = 0.f; g_pos[i] = 0.f; g_npos[i] = 0; }
    if (i < padBytes) g_tn8[padOff + i] = 0;
}

// pos/neg bitmasks directly in COMPACT column space
#define WPW 8
__global__ void pack_compact(const int* __restrict__ label,
                             const int* __restrict__ ids,
                             int B, int C, int NL, int Wc) {
    int row  = blockIdx.y;
    int warp = threadIdx.x >> 5, lane = threadIdx.x & 31;
    int word0 = (blockIdx.x * 8 + warp) * WPW;
    const int* lrow = label + (size_t)row * C;
    unsigned* prow = g_posw + (size_t)row * Wc;
    unsigned* nrow = g_negw + (size_t)row * Wc;
#pragma unroll
    for (int k = 0; k < WPW; ++k) {
        int w = word0 + k;
        if (w >= Wc) break;
        int i = w * 32 + lane;
        bool valid = (i < NL);
        int c   = valid ? ids[i] : 0;
        int lab = valid ? lrow[c] : 1;
        unsigned pos = __ballot_sync(0xffffffffu, valid && lab != 0);
        unsigned neg = __ballot_sync(0xffffffffu, valid && lab == 0);
        if (lane == 0) { prow[w] = pos; nrow[w] = neg; }
    }
}

// warp-per-row normalize -> fp8 (x16). gather=1: row i reads x[ids[i]].
__global__ void norm_fp8_kernel(const float* __restrict__ x,
                                const int* __restrict__ ids,
                                int rows, float eps, int gather, int isText) {
    int i = blockIdx.x * 8 + (threadIdx.x >> 5);
    if (i >= rows) return;
    int lane = threadIdx.x & 31;
    int srcRow = gather ? ids[i] : i;
    const float4* xr = (const float4*)(x + (size_t)srcRow * D_FIX);
    float4 t0 = xr[lane], t1 = xr[lane + 32];
    float ss = t0.x * t0.x + t0.y * t0.y + t0.z * t0.z + t0.w * t0.w
             + t1.x * t1.x + t1.y * t1.y + t1.z * t1.z + t1.w * t1.w;
#pragma unroll
    for (int o = 16; o > 0; o >>= 1) ss += __shfl_xor_sync(0xffffffffu, ss, o);
    float inv = 16.0f / (eps + sqrtf(ss));
    unsigned w0 = pack_e4m3x4(t0.x * inv, t0.y * inv, t0.z * inv, t0.w * inv);
    unsigned w1 = pack_e4m3x4(t1.x * inv, t1.y * inv, t1.z * inv, t1.w * inv);
    unsigned* dst = (unsigned*)(isText ? g_tn8 : g_vn8) + (size_t)i * 64;
    dst[lane]      = w0;
    dst[lane + 32] = w1;
}

// ---------------------------------------------------------------------------
// fp8 GEMM tile 128x128, full K=256 resident, fused loss epilogue.
__global__ __launch_bounds__(256, 2)
void gemm_loss8(int B, int Wc) {
    extern __shared__ unsigned char dynraw[];
    __shared__ float sdn[128], sps[128];
    __shared__ int sns[128];
    __shared__ unsigned s_pos[128][4], s_neg[128][4];

    const int tid = threadIdx.x;
    const int cbase = blockIdx.x * 128;      // compact column base
    const int rbase = blockIdx.y * 128;

    unsigned base = (smemu32(dynraw) + 1023u) & ~1023u;
    const unsigned aB = base;
    const unsigned bB = base + 128u * TS;

    // async tile loads: 8 chunks of 16B per thread per operand
#pragma unroll
    for (int m = 0; m < 8; ++m) {
        int id = m * 256 + tid;
        int r = id >> 4, cb = id & 15;
        CP_ASYNC16(aB + (unsigned)(r * TS + cb * 16),
                   g_vn8 + (size_t)(rbase + r) * D_FIX + cb * 16);
        CP_ASYNC16(bB + (unsigned)(r * TS + cb * 16),
                   g_tn8 + (size_t)(cbase + r) * D_FIX + cb * 16);
    }
    CP_COMMIT();

    if (tid < 128) { sdn[tid] = 0.f; sps[tid] = 0.f; sns[tid] = 0; }
    for (int i = tid; i < 512; i += 256) {
        int r = i >> 2, w = i & 3;
        size_t gi = (size_t)(rbase + r) * Wc + blockIdx.x * 4 + w;
        s_pos[r][w] = g_posw[gi];
        s_neg[r][w] = g_negw[gi];
    }

    float acc[2][8][4];
#pragma unroll
    for (int i = 0; i < 2; i++)
#pragma unroll
        for (int j = 0; j < 8; j++)
#pragma unroll
            for (int k = 0; k < 4; k++) acc[i][j][k] = 0.f;

    const int lane = tid & 31, wid = tid >> 5;
    const int g = lane >> 2, tig = lane & 3;
    const int warp_m = wid & 3, warp_n = wid >> 2;
    const int grp = lane >> 3, rin = lane & 7;

    CP_WAIT0();
    __syncthreads();

    unsigned aBase[2], bBase[4];
#pragma unroll
    for (int mt = 0; mt < 2; ++mt) {
        int rowA = warp_m * 32 + mt * 16 + (grp & 1) * 8 + rin;
        aBase[mt] = aB + (unsigned)(rowA * TS + (grp >> 1) * 16);
    }
#pragma unroll
    for (int p = 0; p < 4; ++p) {
        int rowB = warp_n * 64 + p * 16 + ((grp & 2) ? 8 : 0) + rin;
        bBase[p] = bB + (unsigned)(rowB * TS + (grp & 1) * 16);
    }

#pragma unroll
    for (int ks = 0; ks < 8; ++ks) {          // K = 8 x 32 fp8
        const unsigned kof = ks * 32;
        unsigned a[2][4];
#pragma unroll
        for (int mt = 0; mt < 2; ++mt)
            asm volatile(
                "ldmatrix.sync.aligned.m8n8.x4.shared.b16 {%0,%1,%2,%3}, [%4];\n"
                : "=r"(a[mt][0]), "=r"(a[mt][1]), "=r"(a[mt][2]), "=r"(a[mt][3])
                : "r"(aBase[mt] + kof));
#pragma unroll
        for (int p = 0; p < 4; ++p) {
            unsigned b0, b1, b2, b3;
            asm volatile(
                "ldmatrix.sync.aligned.m8n8.x4.shared.b16 {%0,%1,%2,%3}, [%4];\n"
                : "=r"(b0), "=r"(b1), "=r"(b2), "=r"(b3)
                : "r"(bBase[p] + kof));
            mma_e4m3(acc[0][2 * p],     a[0], b0, b2);
            mma_e4m3(acc[1][2 * p],     a[1], b0, b2);
            mma_e4m3(acc[0][2 * p + 1], a[0], b1, b3);
            mma_e4m3(acc[1][2 * p + 1], a[1], b1, b3);
        }
    }
    __syncthreads();

    // ---- epilogue: masked exp-sum / pos-sum / pos-count (S = acc / 256) ----
    const float sc = 1.0f / 256.0f;
#pragma unroll
    for (int mt = 0; mt < 2; ++mt) {
#pragma unroll
        for (int h = 0; h < 2; ++h) {
            int rl = warp_m * 32 + mt * 16 + h * 8 + g;
            unsigned pw[4], nw[4];
#pragma unroll
            for (int w = 0; w < 4; ++w) { pw[w] = s_pos[rl][w]; nw[w] = s_neg[rl][w]; }
            float dsum = 0.f, psum = 0.f; int np = 0;
#pragma unroll
            for (int nt = 0; nt < 8; ++nt) {
#pragma unroll
                for (int q = 0; q < 2; ++q) {
                    int cl = warp_n * 64 + nt * 8 + 2 * tig + q;
                    int wi = cl >> 5;
                    unsigned m = 1u << (cl & 31);
                    float s = acc[mt][nt][h * 2 + q] * sc;
                    if (pw[wi] & m) { psum += s; np += 1; }
                    else if (nw[wi] & m) dsum += __expf(s);
                }
            }
#pragma unroll
            for (int o = 1; o <= 2; o <<= 1) {
                dsum += __shfl_xor_sync(0xffffffffu, dsum, o);
                psum += __shfl_xor_sync(0xffffffffu, psum, o);
                np   += __shfl_xor_sync(0xffffffffu, np, o);
            }
            if (tig == 0) {
                atomicAdd(&sdn[rl], dsum);
                atomicAdd(&sps[rl], psum);
                atomicAdd(&sns[rl], np);
            }
        }
    }
    __syncthreads();
    if (tid < 128) {
        int grow = rbase + tid;
        if (grow < B) {
            atomicAdd(&g_denom[grow], sdn[tid]);
            atomicAdd(&g_pos[grow], sps[tid]);
            atomicAdd(&g_npos[grow], sns[tid]);
        }
    }
}

// ---------------------------------------------------------------------------
__global__ void finalize_kernel(float* __restrict__ out, int B) {
    __shared__ float red[256];
    int t = threadIdx.x;
    float v = 0.f;
    for (int r = t; r < B; r += 256)
        v += logf(g_denom[r]) - g_pos[r] / (float)g_npos[r];
    red[t] = v;
    __syncthreads();
    for (int s = 128; s > 0; s >>= 1) {
        if (t < s) red[t] += red[t + s];
        __syncthreads();
    }
    if (t == 0) out[0] = red[0] / (float)B;
}

// ---------------------------------------------------------------------------
extern "C" void kernel_launch(void* const* d_in, const int* in_sizes, int n_in,
                              void* d_out, int out_size) {
    const float* vfeat = (const float*)d_in[0];
    const float* tfeat = (const float*)d_in[1];
    const int*   label = (const int*)d_in[2];
    const int*   ids   = (const int*)d_in[3];
    (void)n_in; (void)out_size;

    double s0 = (double)in_sizes[0], s1 = (double)in_sizes[1], s2 = (double)in_sizes[2];
    int D = (int)(sqrt(s0 * s1 / s2) + 0.5);
    if (D <= 0) D = D_FIX;
    int B  = in_sizes[0] / D;
    int C  = in_sizes[1] / D;
    int NL = in_sizes[3];
    float* out = (float*)d_out;

    int ctiles = (NL + 127) / 128;          // compact column tiles
    int Wc = ctiles * 4;
    int padRows = ctiles * 128 - NL;
    int padBytes = padRows * D_FIX;
    size_t padOff = (size_t)NL * D_FIX;

    int mx = (B > padBytes) ? B : padBytes;
    zero_kernel<<<(mx + 255) / 256, 256>>>(B, padBytes, padOff);

    norm_fp8_kernel<<<(B + 7) / 8, 256>>>(vfeat, ids, B, 0.0f, 0, 0);
    norm_fp8_kernel<<<(NL + 7) / 8, 256>>>(tfeat, ids, NL, 1e-6f, 1, 1);

    dim3 pgrid((Wc + 8 * WPW - 1) / (8 * WPW), B);
    pack_compact<<<pgrid, 256>>>(label, ids, B, C, NL, Wc);

    size_t smem_bytes = 1024 + 2 * (size_t)128 * TS;   // 70656
    cudaFuncSetAttribute(gemm_loss8,
                         cudaFuncAttributeMaxDynamicSharedMemorySize,
                         (int)smem_bytes);
    dim3 grid(ctiles, (B + 127) / 128);
    gemm_loss8<<<grid, 256, smem_bytes>>>(B, Wc);

    finalize_kernel<<<1, 256>>>(out, B);
}